// round 16
// baseline (speedup 1.0000x reference)
#include <cuda_runtime.h>
#include <cuda_fp16.h>
#include <cstdint>

typedef unsigned long long ull;

// ---------------------------------------------------------------------------
// Packed f32x2 helpers (stage-5 FFMA path)
// ---------------------------------------------------------------------------
__device__ __forceinline__ void fma2(ull& d, ull a, ull b) {
    asm("fma.rn.f32x2 %0, %1, %2, %3;" : "=l"(d) : "l"(a), "l"(b), "l"(d));
}
__device__ __forceinline__ ull pack2(float v) {
    ull r;
    unsigned u = __float_as_uint(v);
    asm("mov.b64 %0, {%1, %1};" : "=l"(r) : "r"(u));
    return r;
}
__device__ __forceinline__ void unpack2(ull p, float& lo, float& hi) {
    unsigned a, b;
    asm("mov.b64 {%0, %1}, %2;" : "=r"(a), "=r"(b) : "l"(p));
    lo = __uint_as_float(a);
    hi = __uint_as_float(b);
}

__device__ __forceinline__ uint32_t smem_u32(const void* p) {
    uint32_t a;
    asm("{ .reg .u64 t; cvta.to.shared.u64 t, %1; cvt.u32.u64 %0, t; }" : "=r"(a) : "l"(p));
    return a;
}
__device__ __forceinline__ uint32_t f2tf32(float f) {
    uint32_t r;
    asm("cvt.rna.tf32.f32 %0, %1;" : "=r"(r) : "f"(f));
    return r;
}
__device__ __forceinline__ void cp16(uint32_t dst, const void* src) {
    size_t g = __cvta_generic_to_global(src);
    asm volatile("cp.async.ca.shared.global [%0], [%1], 16;" :: "r"(dst), "l"(g) : "memory");
}
__device__ __forceinline__ void mma_tf32(float* d, const uint32_t* a, const uint32_t* b) {
    asm volatile(
        "mma.sync.aligned.m16n8k8.row.col.f32.tf32.tf32.f32 "
        "{%0,%1,%2,%3}, {%4,%5,%6,%7}, {%8,%9}, {%0,%1,%2,%3};"
        : "+f"(d[0]), "+f"(d[1]), "+f"(d[2]), "+f"(d[3])
        : "r"(a[0]), "r"(a[1]), "r"(a[2]), "r"(a[3]), "r"(b[0]), "r"(b[1]));
}

// ---------------------------------------------------------------------------
// Scratch: partial stats, fp16 W (stages 1..4, k-permuted), fp16 Y intermediate
// ---------------------------------------------------------------------------
__device__ float g_psum[348160];
__device__ float g_psq[348160];
__device__ __align__(128) __half g_wh[1048576];     // 4 stages x 16*128*128
__device__ __align__(128) __half g_yh[44564480];

// ---------------------------------------------------------------------------
// W pre-convert: fp32 -> fp16 with in-group-of-8 k permutation
//   stored[g*8 + 2*c + h] = orig[g*8 + h*4 + c]   (c in 0..3, h in 0..1)
// so the mainloop B-pair (k, k+4) is one aligned u32.
// ---------------------------------------------------------------------------
struct WArgs { const float* w[4]; };

__global__ void __launch_bounds__(256)
wconv_kernel(WArgs wa)
{
    int id = blockIdx.x * 256 + threadIdx.x;    // group index, 131072 total
    int s  = id >> 15;                          // 32768 groups per stage
    int gi = id & 32767;
    const float* src = wa.w[s] + (size_t)gi * 8;
    float4 v0 = ((const float4*)src)[0];        // j = 0..3  (h=0)
    float4 v1 = ((const float4*)src)[1];        // j = 4..7  (h=1)
    __half2 h0 = __floats2half2_rn(v0.x, v1.x);
    __half2 h1 = __floats2half2_rn(v0.y, v1.y);
    __half2 h2 = __floats2half2_rn(v0.z, v1.z);
    __half2 h3 = __floats2half2_rn(v0.w, v1.w);
    uint4 pk;
    pk.x = *(const uint32_t*)&h0;
    pk.y = *(const uint32_t*)&h1;
    pk.z = *(const uint32_t*)&h2;
    pk.w = *(const uint32_t*)&h3;
    *((uint4*)(g_wh + ((size_t)s << 18) + (size_t)gi * 8)) = pk;
}

// ---------------------------------------------------------------------------
// Stage-5 FFMA2 path (HW=64, BN=64, no stats) — direct fp32 out
// ---------------------------------------------------------------------------
__device__ __forceinline__ void gemm_tile_ffma64(
    const float* __restrict__ X, const float* __restrict__ W,
    float* __restrict__ Y, int b, float* smem)
{
    constexpr int BK = 16, BN = 64, TN = 8, HW = 64;
    constexpr int TCG = BN / TN;            // 8
    constexpr int TM  = 128 / (256 / TCG);  // 4

    float* Wt = smem;             // [BK][128]
    float* Xs = smem + BK * 128;  // [BK][BN]

    const int tid  = threadIdx.x;
    const int cg   = tid % TCG;
    const int og   = tid / TCG;
    const int orow = og * TM;
    const int pcol = cg * TN;

    const float* Xb = X + (size_t)b * 128 * HW;
    const float* Wb = W + (size_t)b * 128 * 128;

    ull acc[TM][TN / 2];
    #pragma unroll
    for (int m = 0; m < TM; ++m)
        #pragma unroll
        for (int n = 0; n < TN / 2; ++n) acc[m][n] = 0ull;

    for (int kk = 0; kk < 128; kk += BK) {
        #pragma unroll
        for (int j = 0; j < 2; ++j) {
            int i = tid + j * 256;
            int o = i >> 2;
            int q = (i & 3) * 4;
            float4 v = *(const float4*)(Wb + o * 128 + kk + q);
            Wt[(q + 0) * 128 + o] = v.x;
            Wt[(q + 1) * 128 + o] = v.y;
            Wt[(q + 2) * 128 + o] = v.z;
            Wt[(q + 3) * 128 + o] = v.w;
        }
        {
            int i = tid;
            int k  = i / (BN / 4);
            int p4 = i % (BN / 4);
            *(float4*)(Xs + k * BN + p4 * 4) =
                *(const float4*)(Xb + (size_t)(kk + k) * HW + p4 * 4);
        }
        __syncthreads();

        #pragma unroll
        for (int k = 0; k < BK; ++k) {
            float a[TM];
            float4 v = *(const float4*)(Wt + k * 128 + orow);
            a[0] = v.x; a[1] = v.y; a[2] = v.z; a[3] = v.w;
            ull b2[TN / 2];
            const ull* xr = (const ull*)(Xs + k * BN + pcol);
            #pragma unroll
            for (int n = 0; n < TN / 2; ++n) b2[n] = xr[n];
            #pragma unroll
            for (int m = 0; m < TM; ++m) {
                ull a2 = pack2(a[m]);
                #pragma unroll
                for (int n = 0; n < TN / 2; ++n) fma2(acc[m][n], a2, b2[n]);
            }
        }
        __syncthreads();
    }

    float* Yb = Y + (size_t)b * 128 * HW;
    #pragma unroll
    for (int m = 0; m < TM; ++m) {
        float f[TN];
        #pragma unroll
        for (int n = 0; n < TN / 2; ++n) unpack2(acc[m][n], f[2 * n], f[2 * n + 1]);
        float* yrow = Yb + (size_t)(orow + m) * HW + pcol;
        *(float4*)(yrow)     = make_float4(f[0], f[1], f[2], f[3]);
        *(float4*)(yrow + 4) = make_float4(f[4], f[5], f[6], f[7]);
    }
}

// ---------------------------------------------------------------------------
// tf32 mma tile with fp16 W: D[p=128][o=128] = X^T(tile) * W^T, K=128.
//   X chunk: cp.async fp32, [c=32][p=128] pitch 136 (unchanged).
//   W chunk: cp.async fp16 (pre-permuted), [o=128][c'=32] pitch 40 halfs.
//     B frag = one LDS.U32 (a (k, k+4) pair) + exact half2->float2 cvt.
//     Bank map (gr*20 + ca) mod 32 covers all 32 banks — conflict-free.
//   Epilogue: fp16 Ds + coalesced Yh stores (R15 — unchanged).
// ---------------------------------------------------------------------------
__device__ __forceinline__ void gemm_tile_mma(
    const float* __restrict__ X, size_t wh_base,
    size_t yh_off, int HW, int partial_off, int ntiles,
    int tile, int b, float* smem)
{
    constexpr int XP = 136, WPH = 40, PH = 136;
    constexpr int XCHUNK = 32 * XP;            // 4352 floats
    constexpr int WCHUNKF = (128 * WPH) / 2;   // 2560 floats (5120 halfs)
    constexpr int BUFSZ  = XCHUNK + WCHUNKF;   // 6912 floats

    const int tid  = threadIdx.x;
    const int wid  = tid >> 5;
    const int lane = tid & 31;
    const int wr = wid >> 1, wc = wid & 1;
    const int P0 = wr * 32, O0 = wc * 64;

    const float*  Xb = X + (size_t)b * 128 * HW + (size_t)tile * 128;
    const __half* Wb = g_wh + wh_base + ((size_t)b << 14);   // b*128*128

    auto load_chunk = [&](int kk, int buf) {
        float*  Xd  = smem + buf * BUFSZ;
        __half* Whd = (__half*)(Xd + XCHUNK);
        #pragma unroll
        for (int j = 0; j < 4; ++j) {
            int i = tid + j * 256;            // 1024 16B segs: X chunk
            int c  = i >> 5;
            int s4 = (i & 31) * 4;
            cp16(smem_u32(Xd + c * XP + s4), Xb + (size_t)(kk + c) * HW + s4);
        }
        #pragma unroll
        for (int j = 0; j < 2; ++j) {
            int i = tid + j * 256;            // 512 16B segs: W chunk (fp16)
            int o  = i >> 2;
            int sg = (i & 3) * 8;             // halfs
            cp16(smem_u32(Whd + o * WPH + sg), Wb + ((size_t)o << 7) + kk + sg);
        }
        asm volatile("cp.async.commit_group;" ::: "memory");
    };

    float acc[2][8][4];
    #pragma unroll
    for (int mf = 0; mf < 2; ++mf)
        #pragma unroll
        for (int nf = 0; nf < 8; ++nf)
            #pragma unroll
            for (int r = 0; r < 4; ++r) acc[mf][nf][r] = 0.f;

    load_chunk(0, 0);
    load_chunk(32, 1);

    const int ca = lane & 3;
    const int gr = lane >> 2;

    #pragma unroll
    for (int c = 0; c < 4; ++c) {
        if (c < 3) asm volatile("cp.async.wait_group 1;" ::: "memory");
        else       asm volatile("cp.async.wait_group 0;" ::: "memory");
        __syncthreads();

        const float*  Xs = smem + (c & 1) * BUFSZ;
        const __half* Wh = (const __half*)(Xs + XCHUNK);

        #pragma unroll
        for (int ks = 0; ks < 4; ++ks) {
            const int kc = ks * 8;
            uint32_t afr[2][4];
            #pragma unroll
            for (int mf = 0; mf < 2; ++mf) {
                int pr = P0 + mf * 16 + gr;
                afr[mf][0] = f2tf32(Xs[(kc + ca) * XP + pr]);
                afr[mf][1] = f2tf32(Xs[(kc + ca) * XP + pr + 8]);
                afr[mf][2] = f2tf32(Xs[(kc + ca + 4) * XP + pr]);
                afr[mf][3] = f2tf32(Xs[(kc + ca + 4) * XP + pr + 8]);
            }
            #pragma unroll
            for (int nf = 0; nf < 8; ++nf) {
                int orow = O0 + nf * 8 + gr;
                uint32_t wv = *(const uint32_t*)(Wh + orow * WPH + kc + 2 * ca);
                float2 bf = __half22float2(*(const __half2*)&wv);
                uint32_t bfr[2];
                bfr[0] = __float_as_uint(bf.x);   // orig k = kc + ca
                bfr[1] = __float_as_uint(bf.y);   // orig k = kc + ca + 4
                mma_tf32(acc[0][nf], afr[0], bfr);
                mma_tf32(acc[1][nf], afr[1], bfr);
            }
        }
        __syncthreads();
        if (c < 2) load_chunk((c + 2) * 32, c & 1);
    }

    // ---- epilogue: accums -> fp16 Ds[o][p] (pitch PH halfs), reuse smem
    __half* Dh = (__half*)smem;
    #pragma unroll
    for (int mf = 0; mf < 2; ++mf)
        #pragma unroll
        for (int nf = 0; nf < 8; ++nf) {
            int p = P0 + mf * 16 + gr;
            int o = O0 + nf * 8 + ca * 2;
            Dh[o * PH + p]           = __float2half(acc[mf][nf][0]);
            Dh[(o + 1) * PH + p]     = __float2half(acc[mf][nf][1]);
            Dh[o * PH + p + 8]       = __float2half(acc[mf][nf][2]);
            Dh[(o + 1) * PH + p + 8] = __float2half(acc[mf][nf][3]);
        }
    __syncthreads();

    // ---- coalesced fp16 write: per iteration each warp moves 2 rows,
    // 16 lanes x uint4 (16B) per row => 256B contiguous per row.
    {
        __half* Yh = g_yh + yh_off + (size_t)b * 128 * HW + (size_t)tile * 128;
        const int hsel = lane >> 4;
        const int l16  = lane & 15;
        #pragma unroll
        for (int it = 0; it < 8; ++it) {
            int o = it * 16 + wid * 2 + hsel;
            uint4 v = *((const uint4*)(Dh + o * PH) + l16);
            *((uint4*)(Yh + (size_t)o * HW) + l16) = v;

            float2 f0 = __half22float2(*(const __half2*)&v.x);
            float2 f1 = __half22float2(*(const __half2*)&v.y);
            float2 f2 = __half22float2(*(const __half2*)&v.z);
            float2 f3 = __half22float2(*(const __half2*)&v.w);
            float s = f0.x + f0.y + f1.x + f1.y + f2.x + f2.y + f3.x + f3.y;
            float q = f0.x * f0.x + f0.y * f0.y + f1.x * f1.x + f1.y * f1.y
                    + f2.x * f2.x + f2.y * f2.y + f3.x * f3.x + f3.y * f3.y;
            #pragma unroll
            for (int d = 8; d > 0; d >>= 1) {
                s += __shfl_xor_sync(0xFFFFFFFFu, s, d);
                q += __shfl_xor_sync(0xFFFFFFFFu, q, d);
            }
            if (l16 == 0) {
                size_t idx = (size_t)partial_off
                           + ((size_t)b * ntiles + tile) * 128 + o;
                g_psum[idx] = s;
                g_psq[idx]  = q;
            }
        }
    }
}

// ---------------------------------------------------------------------------
// One launch for all five stages (small stages first) — R12 layout.
//   g_wh stage bases: s1=0, s2=262144, s3=524288, s4=786432 (halfs)
// ---------------------------------------------------------------------------
struct KArgs {
    const float* x[5];
    const float* w[5];
};

__global__ void __launch_bounds__(256, 2)
gemm_all_kernel(KArgs a, float* __restrict__ out)
{
    extern __shared__ __align__(16) float dynsmem[];
    int bx = blockIdx.x;
    if (bx < 16) {
        gemm_tile_ffma64(a.x[4], a.w[4], out + 44564480, bx, dynsmem);
    } else if (bx < 48) {
        int l = bx - 16;
        gemm_tile_mma(a.x[3], 786432, 44040192, 256, 344064, 2,
                      l & 1, l >> 1, dynsmem);
    } else if (bx < 176) {
        int l = bx - 48;
        gemm_tile_mma(a.x[2], 524288, 41943040, 1024, 327680, 8,
                      l & 7, l >> 3, dynsmem);
    } else if (bx < 688) {
        int l = bx - 176;
        gemm_tile_mma(a.x[1], 262144, 33554432, 4096, 262144, 32,
                      l & 31, l >> 5, dynsmem);
    } else {
        int l = bx - 688;
        gemm_tile_mma(a.x[0], 0, 0, 16384, 0, 128,
                      l & 127, l >> 7, dynsmem);
    }
}

// ---------------------------------------------------------------------------
// Finalize + normalize stages 1..4 (R12 fused version — unchanged)
// ---------------------------------------------------------------------------
__global__ void __launch_bounds__(256)
norm_all_kernel(float* __restrict__ out)
{
    __shared__ float ssum[128], ssq[128];
    __shared__ float s_m, s_r;

    int bx = blockIdx.x;
    int s  = bx >> 11;
    int ch = bx & 2047;

    int ntiles, HW, poff;
    size_t yoff;
    switch (s) {
        case 0:  ntiles = 128; HW = 16384; yoff = 0;        poff = 0;      break;
        case 1:  ntiles = 32;  HW = 4096;  yoff = 33554432; poff = 262144; break;
        case 2:  ntiles = 8;   HW = 1024;  yoff = 41943040; poff = 327680; break;
        default: ntiles = 2;   HW = 256;   yoff = 44040192; poff = 344064; break;
    }
    int b = ch >> 7, o = ch & 127;
    int tid = threadIdx.x;

    if (tid < 128) {
        float sv = 0.f, qv = 0.f;
        if (tid < ntiles) {
            size_t j = (size_t)poff + ((size_t)b * ntiles + tid) * 128 + o;
            sv = g_psum[j];
            qv = g_psq[j];
        }
        ssum[tid] = sv;
        ssq[tid]  = qv;
    }
    __syncthreads();
    #pragma unroll
    for (int off = 64; off > 0; off >>= 1) {
        if (tid < off) {
            ssum[tid] += ssum[tid + off];
            ssq[tid]  += ssq[tid + off];
        }
        __syncthreads();
    }
    if (tid == 0) {
        float inv = 1.0f / (float)HW;
        float m = ssum[0] * inv;
        float v = fmaf(ssq[0], inv, -m * m);
        s_m = m;
        s_r = rsqrtf(v + 1e-5f);
    }
    __syncthreads();

    float m = s_m, r = s_r;
    const uint2* Yh = (const uint2*)(g_yh + yoff + (size_t)(b * 128 + o) * HW);
    float4* Yo = (float4*)(out + yoff + (size_t)(b * 128 + o) * HW);
    int n4 = HW >> 2;
    for (int i = tid; i < n4; i += 256) {
        uint2 pk = Yh[i];
        float2 f0 = __half22float2(*(const __half2*)&pk.x);
        float2 f1 = __half22float2(*(const __half2*)&pk.y);
        Yo[i] = make_float4((f0.x - m) * r, (f0.y - m) * r,
                            (f1.x - m) * r, (f1.y - m) * r);
    }
}

// ---------------------------------------------------------------------------
// launch: three kernels (wconv -> gemm -> norm)
// ---------------------------------------------------------------------------
extern "C" void kernel_launch(void* const* d_in, const int* in_sizes, int n_in,
                              void* d_out, int out_size)
{
    KArgs args{};
    int wcount = 0;
    for (int i = 0; i < n_in; ++i) {
        const float* p = (const float*)d_in[i];
        switch (in_sizes[i]) {
            case 33554432: args.x[0] = p; break;   // x1
            case 8388608:  args.x[1] = p; break;   // x2
            case 2097152:  args.x[2] = p; break;   // x3
            case 524288:   args.x[3] = p; break;   // x4
            case 131072:   args.x[4] = p; break;   // x5
            case 262144:   if (wcount < 5) args.w[wcount++] = p; break; // l{i}fs
            default: break;
        }
    }

    WArgs wa;
    wa.w[0] = args.w[0];
    wa.w[1] = args.w[1];
    wa.w[2] = args.w[2];
    wa.w[3] = args.w[3];

    // 2 * (4352 + 2560) floats = 55296 bytes
    const int SMEM_BYTES = 55296;
    cudaFuncSetAttribute(gemm_all_kernel,
                         cudaFuncAttributeMaxDynamicSharedMemorySize, SMEM_BYTES);

    float* out = (float*)d_out;
    wconv_kernel<<<512, 256>>>(wa);
    gemm_all_kernel<<<2736, 256, SMEM_BYTES>>>(args, out);
    norm_all_kernel<<<8192, 256>>>(out);

    (void)out_size;
}

// round 17
// speedup vs baseline: 1.0575x; 1.0575x over previous
#include <cuda_runtime.h>
#include <cuda_fp16.h>
#include <cstdint>

typedef unsigned long long ull;

// ---------------------------------------------------------------------------
// Helpers
// ---------------------------------------------------------------------------
__device__ __forceinline__ void fma2(ull& d, ull a, ull b) {
    asm("fma.rn.f32x2 %0, %1, %2, %3;" : "=l"(d) : "l"(a), "l"(b), "l"(d));
}
__device__ __forceinline__ ull pack2(float v) {
    ull r;
    unsigned u = __float_as_uint(v);
    asm("mov.b64 %0, {%1, %1};" : "=l"(r) : "r"(u));
    return r;
}
__device__ __forceinline__ void unpack2(ull p, float& lo, float& hi) {
    unsigned a, b;
    asm("mov.b64 {%0, %1}, %2;" : "=r"(a), "=r"(b) : "l"(p));
    lo = __uint_as_float(a);
    hi = __uint_as_float(b);
}
__device__ __forceinline__ uint32_t smem_u32(const void* p) {
    uint32_t a;
    asm("{ .reg .u64 t; cvta.to.shared.u64 t, %1; cvt.u32.u64 %0, t; }" : "=r"(a) : "l"(p));
    return a;
}
__device__ __forceinline__ void cp16(uint32_t dst, const void* src) {
    size_t g = __cvta_generic_to_global(src);
    asm volatile("cp.async.ca.shared.global [%0], [%1], 16;" :: "r"(dst), "l"(g) : "memory");
}
__device__ __forceinline__ void mma_tf32(float* d, const uint32_t* a, const uint32_t* b) {
    asm volatile(
        "mma.sync.aligned.m16n8k8.row.col.f32.tf32.tf32.f32 "
        "{%0,%1,%2,%3}, {%4,%5,%6,%7}, {%8,%9}, {%0,%1,%2,%3};"
        : "+f"(d[0]), "+f"(d[1]), "+f"(d[2]), "+f"(d[3])
        : "r"(a[0]), "r"(a[1]), "r"(a[2]), "r"(a[3]), "r"(b[0]), "r"(b[1]));
}
__device__ __forceinline__ uint2 ldg_cs_u2(const void* p) {
    uint2 v;
    asm volatile("ld.global.cs.v2.u32 {%0, %1}, [%2];"
                 : "=r"(v.x), "=r"(v.y) : "l"(p));
    return v;
}
__device__ __forceinline__ void stg_cs_f4(void* p, float4 v) {
    asm volatile("st.global.cs.v4.f32 [%0], {%1, %2, %3, %4};"
                 :: "l"(p), "f"(v.x), "f"(v.y), "f"(v.z), "f"(v.w) : "memory");
}

// ---------------------------------------------------------------------------
// Scratch
// ---------------------------------------------------------------------------
__device__ float g_psum[348160];
__device__ float g_psq[348160];
__device__ __align__(128) __half g_wh[1048576];     // 4 stages x 16*128*128
__device__ __align__(128) __half g_yh[44564480];

// ---------------------------------------------------------------------------
// W pre-convert: fp32 -> fp16 with in-group-of-8 k permutation.
// 2 groups per thread (MLP 4), 256 blocks x 256 threads.
// ---------------------------------------------------------------------------
struct WArgs { const float* w[4]; };

__global__ void __launch_bounds__(256)
wconv_kernel(WArgs wa)
{
    int base = (blockIdx.x * 256 + threadIdx.x) * 2;    // 2 groups/thread
    #pragma unroll
    for (int gidx = 0; gidx < 2; ++gidx) {
        int id = base + gidx;
        int s  = id >> 15;
        int gi = id & 32767;
        const float* src = wa.w[s] + (size_t)gi * 8;
        float4 v0 = ((const float4*)src)[0];
        float4 v1 = ((const float4*)src)[1];
        __half2 h0 = __floats2half2_rn(v0.x, v1.x);
        __half2 h1 = __floats2half2_rn(v0.y, v1.y);
        __half2 h2 = __floats2half2_rn(v0.z, v1.z);
        __half2 h3 = __floats2half2_rn(v0.w, v1.w);
        uint4 pk;
        pk.x = *(const uint32_t*)&h0;
        pk.y = *(const uint32_t*)&h1;
        pk.z = *(const uint32_t*)&h2;
        pk.w = *(const uint32_t*)&h3;
        *((uint4*)(g_wh + ((size_t)s << 18) + (size_t)gi * 8)) = pk;
    }
}

// ---------------------------------------------------------------------------
// Stage-5 FFMA2 path (HW=64, BN=64, no stats) — direct fp32 out
// ---------------------------------------------------------------------------
__device__ __forceinline__ void gemm_tile_ffma64(
    const float* __restrict__ X, const float* __restrict__ W,
    float* __restrict__ Y, int b, float* smem)
{
    constexpr int BK = 16, BN = 64, TN = 8, HW = 64;
    constexpr int TCG = BN / TN;            // 8
    constexpr int TM  = 128 / (256 / TCG);  // 4

    float* Wt = smem;             // [BK][128]
    float* Xs = smem + BK * 128;  // [BK][BN]

    const int tid  = threadIdx.x;
    const int cg   = tid % TCG;
    const int og   = tid / TCG;
    const int orow = og * TM;
    const int pcol = cg * TN;

    const float* Xb = X + (size_t)b * 128 * HW;
    const float* Wb = W + (size_t)b * 128 * 128;

    ull acc[TM][TN / 2];
    #pragma unroll
    for (int m = 0; m < TM; ++m)
        #pragma unroll
        for (int n = 0; n < TN / 2; ++n) acc[m][n] = 0ull;

    for (int kk = 0; kk < 128; kk += BK) {
        #pragma unroll
        for (int j = 0; j < 2; ++j) {
            int i = tid + j * 256;
            int o = i >> 2;
            int q = (i & 3) * 4;
            float4 v = *(const float4*)(Wb + o * 128 + kk + q);
            Wt[(q + 0) * 128 + o] = v.x;
            Wt[(q + 1) * 128 + o] = v.y;
            Wt[(q + 2) * 128 + o] = v.z;
            Wt[(q + 3) * 128 + o] = v.w;
        }
        {
            int i = tid;
            int k  = i / (BN / 4);
            int p4 = i % (BN / 4);
            *(float4*)(Xs + k * BN + p4 * 4) =
                *(const float4*)(Xb + (size_t)(kk + k) * HW + p4 * 4);
        }
        __syncthreads();

        #pragma unroll
        for (int k = 0; k < BK; ++k) {
            float a[TM];
            float4 v = *(const float4*)(Wt + k * 128 + orow);
            a[0] = v.x; a[1] = v.y; a[2] = v.z; a[3] = v.w;
            ull b2[TN / 2];
            const ull* xr = (const ull*)(Xs + k * BN + pcol);
            #pragma unroll
            for (int n = 0; n < TN / 2; ++n) b2[n] = xr[n];
            #pragma unroll
            for (int m = 0; m < TM; ++m) {
                ull a2 = pack2(a[m]);
                #pragma unroll
                for (int n = 0; n < TN / 2; ++n) fma2(acc[m][n], a2, b2[n]);
            }
        }
        __syncthreads();
    }

    float* Yb = Y + (size_t)b * 128 * HW;
    #pragma unroll
    for (int m = 0; m < TM; ++m) {
        float f[TN];
        #pragma unroll
        for (int n = 0; n < TN / 2; ++n) unpack2(acc[m][n], f[2 * n], f[2 * n + 1]);
        float* yrow = Yb + (size_t)(orow + m) * HW + pcol;
        *(float4*)(yrow)     = make_float4(f[0], f[1], f[2], f[3]);
        *(float4*)(yrow + 4) = make_float4(f[4], f[5], f[6], f[7]);
    }
}

// ---------------------------------------------------------------------------
// tf32 mma tile with fp16 W: D[p=128][o=128] = X^T(tile) * W^T, K=128.
//   A: raw fp32 bits from smem (HW RZ-truncates to tf32; uniform bias
//      divides out under instance norm).  B: fp16 pair -> exact cvt.
//   Epilogue: fp16 Ds + coalesced Yh stores (R15/R16 — unchanged).
// ---------------------------------------------------------------------------
__device__ __forceinline__ void gemm_tile_mma(
    const float* __restrict__ X, size_t wh_base,
    size_t yh_off, int HW, int partial_off, int ntiles,
    int tile, int b, float* smem)
{
    constexpr int XP = 136, WPH = 40, PH = 136;
    constexpr int XCHUNK = 32 * XP;            // 4352 floats
    constexpr int WCHUNKF = (128 * WPH) / 2;   // 2560 floats
    constexpr int BUFSZ  = XCHUNK + WCHUNKF;   // 6912 floats

    const int tid  = threadIdx.x;
    const int wid  = tid >> 5;
    const int lane = tid & 31;
    const int wr = wid >> 1, wc = wid & 1;
    const int P0 = wr * 32, O0 = wc * 64;

    const float*  Xb = X + (size_t)b * 128 * HW + (size_t)tile * 128;
    const __half* Wb = g_wh + wh_base + ((size_t)b << 14);

    auto load_chunk = [&](int kk, int buf) {
        float*  Xd  = smem + buf * BUFSZ;
        __half* Whd = (__half*)(Xd + XCHUNK);
        #pragma unroll
        for (int j = 0; j < 4; ++j) {
            int i = tid + j * 256;
            int c  = i >> 5;
            int s4 = (i & 31) * 4;
            cp16(smem_u32(Xd + c * XP + s4), Xb + (size_t)(kk + c) * HW + s4);
        }
        #pragma unroll
        for (int j = 0; j < 2; ++j) {
            int i = tid + j * 256;
            int o  = i >> 2;
            int sg = (i & 3) * 8;
            cp16(smem_u32(Whd + o * WPH + sg), Wb + ((size_t)o << 7) + kk + sg);
        }
        asm volatile("cp.async.commit_group;" ::: "memory");
    };

    float acc[2][8][4];
    #pragma unroll
    for (int mf = 0; mf < 2; ++mf)
        #pragma unroll
        for (int nf = 0; nf < 8; ++nf)
            #pragma unroll
            for (int r = 0; r < 4; ++r) acc[mf][nf][r] = 0.f;

    load_chunk(0, 0);
    load_chunk(32, 1);

    const int ca = lane & 3;
    const int gr = lane >> 2;

    #pragma unroll
    for (int c = 0; c < 4; ++c) {
        if (c < 3) asm volatile("cp.async.wait_group 1;" ::: "memory");
        else       asm volatile("cp.async.wait_group 0;" ::: "memory");
        __syncthreads();

        const float*  Xs = smem + (c & 1) * BUFSZ;
        const uint32_t* Xu = (const uint32_t*)Xs;     // raw bits -> HW RZ
        const __half* Wh = (const __half*)(Xs + XCHUNK);

        #pragma unroll
        for (int ks = 0; ks < 4; ++ks) {
            const int kc = ks * 8;
            uint32_t afr[2][4];
            #pragma unroll
            for (int mf = 0; mf < 2; ++mf) {
                int pr = P0 + mf * 16 + gr;
                afr[mf][0] = Xu[(kc + ca) * XP + pr];
                afr[mf][1] = Xu[(kc + ca) * XP + pr + 8];
                afr[mf][2] = Xu[(kc + ca + 4) * XP + pr];
                afr[mf][3] = Xu[(kc + ca + 4) * XP + pr + 8];
            }
            #pragma unroll
            for (int nf = 0; nf < 8; ++nf) {
                int orow = O0 + nf * 8 + gr;
                uint32_t wv = *(const uint32_t*)(Wh + orow * WPH + kc + 2 * ca);
                float2 bf = __half22float2(*(const __half2*)&wv);
                uint32_t bfr[2];
                bfr[0] = __float_as_uint(bf.x);
                bfr[1] = __float_as_uint(bf.y);
                mma_tf32(acc[0][nf], afr[0], bfr);
                mma_tf32(acc[1][nf], afr[1], bfr);
            }
        }
        __syncthreads();
        if (c < 2) load_chunk((c + 2) * 32, c & 1);
    }

    // ---- epilogue: accums -> fp16 Ds[o][p] (pitch PH halfs), reuse smem
    __half* Dh = (__half*)smem;
    #pragma unroll
    for (int mf = 0; mf < 2; ++mf)
        #pragma unroll
        for (int nf = 0; nf < 8; ++nf) {
            int p = P0 + mf * 16 + gr;
            int o = O0 + nf * 8 + ca * 2;
            Dh[o * PH + p]           = __float2half(acc[mf][nf][0]);
            Dh[(o + 1) * PH + p]     = __float2half(acc[mf][nf][1]);
            Dh[o * PH + p + 8]       = __float2half(acc[mf][nf][2]);
            Dh[(o + 1) * PH + p + 8] = __float2half(acc[mf][nf][3]);
        }
    __syncthreads();

    // ---- coalesced fp16 write: per iteration each warp moves 2 rows.
    {
        __half* Yh = g_yh + yh_off + (size_t)b * 128 * HW + (size_t)tile * 128;
        const int hsel = lane >> 4;
        const int l16  = lane & 15;
        #pragma unroll
        for (int it = 0; it < 8; ++it) {
            int o = it * 16 + wid * 2 + hsel;
            uint4 v = *((const uint4*)(Dh + o * PH) + l16);
            *((uint4*)(Yh + (size_t)o * HW) + l16) = v;

            float2 f0 = __half22float2(*(const __half2*)&v.x);
            float2 f1 = __half22float2(*(const __half2*)&v.y);
            float2 f2 = __half22float2(*(const __half2*)&v.z);
            float2 f3 = __half22float2(*(const __half2*)&v.w);
            float s = f0.x + f0.y + f1.x + f1.y + f2.x + f2.y + f3.x + f3.y;
            float q = f0.x * f0.x + f0.y * f0.y + f1.x * f1.x + f1.y * f1.y
                    + f2.x * f2.x + f2.y * f2.y + f3.x * f3.x + f3.y * f3.y;
            #pragma unroll
            for (int d = 8; d > 0; d >>= 1) {
                s += __shfl_xor_sync(0xFFFFFFFFu, s, d);
                q += __shfl_xor_sync(0xFFFFFFFFu, q, d);
            }
            if (l16 == 0) {
                size_t idx = (size_t)partial_off
                           + ((size_t)b * ntiles + tile) * 128 + o;
                g_psum[idx] = s;
                g_psq[idx]  = q;
            }
        }
    }
}

// ---------------------------------------------------------------------------
// One launch for all five stages (small stages first) — R12 layout.
// ---------------------------------------------------------------------------
struct KArgs {
    const float* x[5];
    const float* w[5];
};

__global__ void __launch_bounds__(256, 2)
gemm_all_kernel(KArgs a, float* __restrict__ out)
{
    extern __shared__ __align__(16) float dynsmem[];
    int bx = blockIdx.x;
    if (bx < 16) {
        gemm_tile_ffma64(a.x[4], a.w[4], out + 44564480, bx, dynsmem);
    } else if (bx < 48) {
        int l = bx - 16;
        gemm_tile_mma(a.x[3], 786432, 44040192, 256, 344064, 2,
                      l & 1, l >> 1, dynsmem);
    } else if (bx < 176) {
        int l = bx - 48;
        gemm_tile_mma(a.x[2], 524288, 41943040, 1024, 327680, 8,
                      l & 7, l >> 3, dynsmem);
    } else if (bx < 688) {
        int l = bx - 176;
        gemm_tile_mma(a.x[1], 262144, 33554432, 4096, 262144, 32,
                      l & 31, l >> 5, dynsmem);
    } else {
        int l = bx - 688;
        gemm_tile_mma(a.x[0], 0, 0, 16384, 0, 128,
                      l & 127, l >> 7, dynsmem);
    }
}

// ---------------------------------------------------------------------------
// Finalize + normalize stages 1..4 with streaming cache hints.
// ---------------------------------------------------------------------------
__global__ void __launch_bounds__(256)
norm_all_kernel(float* __restrict__ out)
{
    __shared__ float ssum[128], ssq[128];
    __shared__ float s_m, s_r;

    int bx = blockIdx.x;
    int s  = bx >> 11;
    int ch = bx & 2047;

    int ntiles, HW, poff;
    size_t yoff;
    switch (s) {
        case 0:  ntiles = 128; HW = 16384; yoff = 0;        poff = 0;      break;
        case 1:  ntiles = 32;  HW = 4096;  yoff = 33554432; poff = 262144; break;
        case 2:  ntiles = 8;   HW = 1024;  yoff = 41943040; poff = 327680; break;
        default: ntiles = 2;   HW = 256;   yoff = 44040192; poff = 344064; break;
    }
    int b = ch >> 7, o = ch & 127;
    int tid = threadIdx.x;

    if (tid < 128) {
        float sv = 0.f, qv = 0.f;
        if (tid < ntiles) {
            size_t j = (size_t)poff + ((size_t)b * ntiles + tid) * 128 + o;
            sv = g_psum[j];
            qv = g_psq[j];
        }
        ssum[tid] = sv;
        ssq[tid]  = qv;
    }
    __syncthreads();
    #pragma unroll
    for (int off = 64; off > 0; off >>= 1) {
        if (tid < off) {
            ssum[tid] += ssum[tid + off];
            ssq[tid]  += ssq[tid + off];
        }
        __syncthreads();
    }
    if (tid == 0) {
        float inv = 1.0f / (float)HW;
        float m = ssum[0] * inv;
        float v = fmaf(ssq[0], inv, -m * m);
        s_m = m;
        s_r = rsqrtf(v + 1e-5f);
    }
    __syncthreads();

    float m = s_m, r = s_r;
    const uint2* Yh = (const uint2*)(g_yh + yoff + (size_t)(b * 128 + o) * HW);
    float4* Yo = (float4*)(out + yoff + (size_t)(b * 128 + o) * HW);
    int n4 = HW >> 2;
    for (int i = tid; i < n4; i += 256) {
        uint2 pk = ldg_cs_u2(Yh + i);
        float2 f0 = __half22float2(*(const __half2*)&pk.x);
        float2 f1 = __half22float2(*(const __half2*)&pk.y);
        stg_cs_f4(Yo + i, make_float4((f0.x - m) * r, (f0.y - m) * r,
                                      (f1.x - m) * r, (f1.y - m) * r));
    }
}

// ---------------------------------------------------------------------------
// launch: three kernels (wconv -> gemm -> norm)
// ---------------------------------------------------------------------------
extern "C" void kernel_launch(void* const* d_in, const int* in_sizes, int n_in,
                              void* d_out, int out_size)
{
    KArgs args{};
    int wcount = 0;
    for (int i = 0; i < n_in; ++i) {
        const float* p = (const float*)d_in[i];
        switch (in_sizes[i]) {
            case 33554432: args.x[0] = p; break;   // x1
            case 8388608:  args.x[1] = p; break;   // x2
            case 2097152:  args.x[2] = p; break;   // x3
            case 524288:   args.x[3] = p; break;   // x4
            case 131072:   args.x[4] = p; break;   // x5
            case 262144:   if (wcount < 5) args.w[wcount++] = p; break; // l{i}fs
            default: break;
        }
    }

    WArgs wa;
    wa.w[0] = args.w[0];
    wa.w[1] = args.w[1];
    wa.w[2] = args.w[2];
    wa.w[3] = args.w[3];

    // 2 * (4352 + 2560) floats = 55296 bytes
    const int SMEM_BYTES = 55296;
    cudaFuncSetAttribute(gemm_all_kernel,
                         cudaFuncAttributeMaxDynamicSharedMemorySize, SMEM_BYTES);

    float* out = (float*)d_out;
    wconv_kernel<<<256, 256>>>(wa);
    gemm_all_kernel<<<2736, 256, SMEM_BYTES>>>(args, out);
    norm_all_kernel<<<8192, 256>>>(out);

    (void)out_size;
}